// round 15
// baseline (speedup 1.0000x reference)
#include <cuda_runtime.h>
#include <cuda_bf16.h>
#include <cstdint>
#include <math.h>
#include <float.h>

// Problem constants
#define BB 2
#define N1 16384
#define N2 4096
#define C1 128
#define C2 256
#define M_OUT 256
#define K1 384
#define K2 256
#define TOT (BB * M_OUT * N1)

// ---------------- device scratch ----------------
__device__ float g_x2t[BB * N2 * C2];       // x2 transposed (B, N2, C2)
__device__ int   g_idx[BB * N1 * 3];
__device__ float g_w[BB * N1 * 3];
__device__ float g_y1[BB * M_OUT * N1];     // (B, 256, N1) n-contig fp32
__device__ float g_scale[M_OUT];
__device__ float g_shift[M_OUT];
__device__ float g_s1[M_OUT], g_ss1[M_OUT]; // BN1 accumulators
__device__ float g_s2[M_OUT], g_ss2[M_OUT]; // BN2 accumulators

// Pre-converted bf16 hi/lo operand planes (k-contig rows)
__device__ __nv_bfloat16 g_xb1_hi[BB * N1 * K1];
__device__ __nv_bfloat16 g_xb1_lo[BB * N1 * K1];
__device__ __nv_bfloat16 g_xb2_hi[BB * N1 * K2];
__device__ __nv_bfloat16 g_xb2_lo[BB * N1 * K2];
__device__ __nv_bfloat16 g_w1_hi[M_OUT * K1];
__device__ __nv_bfloat16 g_w1_lo[M_OUT * K1];
__device__ __nv_bfloat16 g_w2_hi[M_OUT * K2];
__device__ __nv_bfloat16 g_w2_lo[M_OUT * K2];

// ---------------- helpers ----------------
__device__ __forceinline__ uint32_t smem_u32(const void* p) {
    uint32_t a;
    asm("{ .reg .u64 t; cvta.to.shared.u64 t, %1; cvt.u32.u64 %0, t; }" : "=r"(a) : "l"(p));
    return a;
}
#define LDSM_X4(R, ADDR) \
    asm volatile("ldmatrix.sync.aligned.m8n8.x4.shared.b16 {%0,%1,%2,%3}, [%4];" \
        : "=r"((R)[0]), "=r"((R)[1]), "=r"((R)[2]), "=r"((R)[3]) : "r"(ADDR))
#define MMA16816(C, A, B0, B1) \
    asm volatile("mma.sync.aligned.m16n8k16.row.col.f32.bf16.bf16.f32 " \
        "{%0,%1,%2,%3}, {%4,%5,%6,%7}, {%8,%9}, {%0,%1,%2,%3};" \
        : "+f"((C)[0]), "+f"((C)[1]), "+f"((C)[2]), "+f"((C)[3]) \
        : "r"((A)[0]), "r"((A)[1]), "r"((A)[2]), "r"((A)[3]), "r"(B0), "r"(B1))
#define CP16(dst, src) \
    asm volatile("cp.async.cg.shared.global [%0], [%1], 16;" :: "r"(dst), "l"(src))
#define CPCOMMIT() asm volatile("cp.async.commit_group;" ::: "memory")
#define CPWAIT1()  asm volatile("cp.async.wait_group 1;" ::: "memory")

// packed f32x2 ops (each lane = independent .rn op, bit-exact vs scalar)
#define MUL2(D, A, B)    asm("mul.rn.f32x2 %0, %1, %2;"     : "=l"(D) : "l"(A), "l"(B))
#define FMA2V(D, A, B, C) asm("fma.rn.f32x2 %0, %1, %2, %3;" : "=l"(D) : "l"(A), "l"(B), "l"(C))
#define ADD2(D, A, B)    asm("add.rn.f32x2 %0, %1, %2;"     : "=l"(D) : "l"(A), "l"(B))
#define DUPP(D, S)       asm("mov.b64 %0, {%1, %1};"        : "=l"(D) : "f"(S))
#define UNPK(LO, HI, S)  asm("mov.b64 {%0, %1}, %2;"        : "=f"(LO), "=f"(HI) : "l"(S))

__device__ __forceinline__ void split1(float x, __nv_bfloat16& hi, __nv_bfloat16& lo) {
    hi = __float2bfloat16(x);
    lo = __float2bfloat16(x - __bfloat162float(hi));
}
__device__ __forceinline__ void split2(float x, float y, uint32_t& hi, uint32_t& lo) {
    __nv_bfloat16 hx, lx, hy, ly;
    split1(x, hx, lx); split1(y, hy, ly);
    hi = ((uint32_t)__bfloat16_as_ushort(hy) << 16) | __bfloat16_as_ushort(hx);
    lo = ((uint32_t)__bfloat16_as_ushort(ly) << 16) | __bfloat16_as_ushort(lx);
}
// smem offset: row*128 B, 8 chunks of 16 B, chunk ^= row&7 (XOR swizzle)
__device__ __forceinline__ uint32_t swz(int row, int chunk) {
    return (uint32_t)(row * 128 + ((chunk ^ (row & 7)) << 4));
}

// top-3 chain state + update (strict <, earliest index wins within a chain)
struct Top3 { float d0, d1, d2; int i0, i1, i2; };
__device__ __forceinline__ void t3_init(Top3& t) {
    t.d0 = t.d1 = t.d2 = FLT_MAX; t.i0 = t.i1 = t.i2 = 0;
}
__device__ __forceinline__ void t3_push(Top3& t, float d, int jg) {
    if (d < t.d2) {
        if (d < t.d1) {
            t.d2 = t.d1; t.i2 = t.i1;
            if (d < t.d0) { t.d1 = t.d0; t.i1 = t.i0; t.d0 = d; t.i0 = jg; }
            else          { t.d1 = d;  t.i1 = jg; }
        } else {
            t.d2 = d; t.i2 = jg;
        }
    }
}
// comparator matching global-scan semantics: smaller d first; tie -> smaller idx
__device__ __forceinline__ bool t3_less(float da, int ia, float db, int ib) {
    return (da < db) || (da == db && ia < ib);
}

// =========================================================================
// 0) Zero BN accumulators (graph-safe, runs every launch)
// =========================================================================
__global__ void zero_acc_kernel()
{
    const int t = threadIdx.x;
    g_s1[t] = 0.f; g_ss1[t] = 0.f;
    g_s2[t] = 0.f; g_ss2[t] = 0.f;
}

// =========================================================================
// 1) KNN — reference-exact distance arithmetic, f32x2-packed, with TWO
//    independent top-3 chains (even/odd pairs) merged exactly at the end.
// =========================================================================
#define KNN_CHUNK 2048

__global__ void __launch_bounds__(128) knn_kernel(const float* __restrict__ p1,
                                                  const float* __restrict__ p2)
{
    __shared__ ulonglong2 s_xy[KNN_CHUNK / 2];   // {x01, y01}
    __shared__ ulonglong2 s_zb[KNN_CHUNK / 2];   // {z01, bb01}

    const int b = blockIdx.y;
    const int n = blockIdx.x * 128 + threadIdx.x;

    const size_t qoff = ((size_t)b * N1 + n) * 3;
    const float qx = p1[qoff + 0];
    const float qy = p1[qoff + 1];
    const float qz = p1[qoff + 2];
    float tq = __fadd_rn(__fmul_rn(qx, qx), __fmul_rn(qy, qy));
    const float qq = __fadd_rn(tq, __fmul_rn(qz, qz));

    unsigned long long qx2, qy2, qz2, qq2, neg2;
    DUPP(qx2, qx); DUPP(qy2, qy); DUPP(qz2, qz); DUPP(qq2, qq);
    DUPP(neg2, -2.0f);

    Top3 A, Bt;
    t3_init(A); t3_init(Bt);

    const float* p2b = p2 + (size_t)b * N2 * 3;

    #pragma unroll
    for (int chunk = 0; chunk < N2 / KNN_CHUNK; ++chunk) {
        if (chunk > 0) __syncthreads();
        const int jbase = chunk * KNN_CHUNK;
        for (int jp = threadIdx.x; jp < KNN_CHUNK / 2; jp += 128) {
            const float* r = p2b + (jbase + jp * 2) * 3;
            float x0 = r[0], y0 = r[1], z0 = r[2];
            float x1 = r[3], y1 = r[4], z1 = r[5];
            float b0 = __fadd_rn(__fadd_rn(__fmul_rn(x0, x0), __fmul_rn(y0, y0)), __fmul_rn(z0, z0));
            float b1 = __fadd_rn(__fadd_rn(__fmul_rn(x1, x1), __fmul_rn(y1, y1)), __fmul_rn(z1, z1));
            *(float2*)&s_xy[jp].x = make_float2(x0, x1);
            *(float2*)&s_xy[jp].y = make_float2(y0, y1);
            *(float2*)&s_zb[jp].x = make_float2(z0, z1);
            *(float2*)&s_zb[jp].y = make_float2(b0, b1);
        }
        __syncthreads();

        // two pairs (4 refs) per iteration; chain A <- pair jp, chain B <- pair jp+1
        #pragma unroll 2
        for (int jp = 0; jp < KNN_CHUNK / 2; jp += 2) {
            ulonglong2 xyA = s_xy[jp],     zbA = s_zb[jp];
            ulonglong2 xyB = s_xy[jp + 1], zbB = s_zb[jp + 1];
            unsigned long long dotA, sA, mA, dA;
            unsigned long long dotB, sB, mB, dB;
            MUL2(dotA, qx2, xyA.x);  MUL2(dotB, qx2, xyB.x);
            FMA2V(dotA, qy2, xyA.y, dotA);  FMA2V(dotB, qy2, xyB.y, dotB);
            FMA2V(dotA, qz2, zbA.x, dotA);  FMA2V(dotB, qz2, zbB.x, dotB);
            ADD2(sA, qq2, zbA.y);  ADD2(sB, qq2, zbB.y);
            MUL2(mA, dotA, neg2);  MUL2(mB, dotB, neg2);
            ADD2(dA, sA, mA);      ADD2(dB, sB, mB);
            float al, ah, bl, bh;
            UNPK(al, ah, dA);
            UNPK(bl, bh, dB);
            const int jgA = jbase + jp * 2;
            const int jgB = jbase + jp * 2 + 2;
            t3_push(A, al, jgA);
            t3_push(Bt, bl, jgB);
            t3_push(A, ah, jgA + 1);
            t3_push(Bt, bh, jgB + 1);
        }
    }

    // ---- exact merge of the two chains (6 candidates -> top 3) ----
    float md[3]; int mi[3];
    {
        float ad[3] = {A.d0, A.d1, A.d2};   int ai[3] = {A.i0, A.i1, A.i2};
        float bd[3] = {Bt.d0, Bt.d1, Bt.d2}; int bi[3] = {Bt.i0, Bt.i1, Bt.i2};
        int ia = 0, ib = 0;
        #pragma unroll
        for (int k = 0; k < 3; ++k) {
            if (t3_less(ad[ia], ai[ia], bd[ib], bi[ib])) { md[k] = ad[ia]; mi[k] = ai[ia]; ++ia; }
            else                                          { md[k] = bd[ib]; mi[k] = bi[ib]; ++ib; }
        }
    }

    float d0 = fmaxf(md[0], 0.0f);
    float d1 = fmaxf(md[1], 0.0f);
    float d2 = fmaxf(md[2], 0.0f);
    float w0 = 1.f / (d0 + 1e-16f);
    float w1 = 1.f / (d1 + 1e-16f);
    float w2 = 1.f / (d2 + 1e-16f);
    float ws = 1.f / (w0 + w1 + w2);

    const int base = (b * N1 + n) * 3;
    g_w[base + 0] = w0 * ws;
    g_w[base + 1] = w1 * ws;
    g_w[base + 2] = w2 * ws;
    g_idx[base + 0] = mi[0];
    g_idx[base + 1] = mi[1];
    g_idx[base + 2] = mi[2];
}

// =========================================================================
// 2) Transpose x2 (B, C2, N2) -> (B, N2, C2)
// =========================================================================
__global__ void transpose_x2_kernel(const float* __restrict__ x2)
{
    __shared__ float tile[32][33];
    const int b  = blockIdx.z;
    const int c0 = blockIdx.y * 32;
    const int n0 = blockIdx.x * 32;
    const int tx = threadIdx.x;
    const int ty = threadIdx.y;

    #pragma unroll
    for (int i = ty; i < 32; i += 8)
        tile[i][tx] = x2[((size_t)b * C2 + c0 + i) * N2 + n0 + tx];
    __syncthreads();
    #pragma unroll
    for (int i = ty; i < 32; i += 8)
        g_x2t[((size_t)b * N2 + n0 + i) * C2 + c0 + tx] = tile[tx][i];
}

// =========================================================================
// 3) Gather + interpolate -> bf16 hi/lo planes of GEMM1 B (k in [128,384))
// =========================================================================
__global__ void __launch_bounds__(256) gather_xb1_kernel()
{
    const int q    = blockIdx.x * 8 + (threadIdx.x >> 5);
    const int lane = threadIdx.x & 31;
    const int b = q / N1;
    const int n = q % N1;

    const int base = q * 3;
    const float w0 = g_w[base + 0];
    const float w1 = g_w[base + 1];
    const float w2 = g_w[base + 2];
    const float* f0 = g_x2t + ((size_t)b * N2 + g_idx[base + 0]) * C2;
    const float* f1 = g_x2t + ((size_t)b * N2 + g_idx[base + 1]) * C2;
    const float* f2 = g_x2t + ((size_t)b * N2 + g_idx[base + 2]) * C2;
    const size_t obase = ((size_t)b * N1 + n) * K1 + C1;

    #pragma unroll
    for (int it = 0; it < 4; ++it) {
        const int c = it * 64 + lane * 2;
        float2 a0 = *(const float2*)&f0[c];
        float2 a1 = *(const float2*)&f1[c];
        float2 a2 = *(const float2*)&f2[c];
        float v0 = fmaf(w0, a0.x, fmaf(w1, a1.x, w2 * a2.x));
        float v1 = fmaf(w0, a0.y, fmaf(w1, a1.y, w2 * a2.y));
        uint32_t h, l;
        split2(v0, v1, h, l);
        *(uint32_t*)&g_xb1_hi[obase + c] = h;
        *(uint32_t*)&g_xb1_lo[obase + c] = l;
    }
}

// =========================================================================
// 4) Transpose-convert n-major fp32 -> k-contig bf16 hi/lo planes
// =========================================================================
template<bool BN>
__global__ void convert_nmajor_kernel(const float* __restrict__ src,
                                      __nv_bfloat16* __restrict__ dhi,
                                      __nv_bfloat16* __restrict__ dlo,
                                      int C, int Kdst)
{
    __shared__ float tile[32][33];
    const int b  = blockIdx.z;
    const int c0 = blockIdx.y * 32;
    const int n0 = blockIdx.x * 32;
    const int tx = threadIdx.x;   // 32
    const int ty = threadIdx.y;   // 8

    #pragma unroll
    for (int i = ty; i < 32; i += 8) {
        float v = src[((size_t)b * C + c0 + i) * N1 + n0 + tx];
        if (BN) v = fmaxf(fmaf(v, g_scale[c0 + i], g_shift[c0 + i]), 0.f);
        tile[i][tx] = v;
    }
    __syncthreads();

    const int tid = ty * 32 + tx;
    if (tid < 128) {
        const int r = tid >> 2;   // n row 0..31
        const int q = tid & 3;    // 8-k chunk
        uint32_t hw[4], lw[4];
        #pragma unroll
        for (int j = 0; j < 4; ++j)
            split2(tile[q * 8 + j * 2][r], tile[q * 8 + j * 2 + 1][r], hw[j], lw[j]);
        const size_t o = ((size_t)b * N1 + n0 + r) * Kdst + c0 + q * 8;
        *(uint4*)&dhi[o] = make_uint4(hw[0], hw[1], hw[2], hw[3]);
        *(uint4*)&dlo[o] = make_uint4(lw[0], lw[1], lw[2], lw[3]);
    }
}

// =========================================================================
// 5) Convert W fp32 -> bf16 hi/lo (flat)
// =========================================================================
__global__ void convert_w_kernel(const float* __restrict__ W,
                                 __nv_bfloat16* __restrict__ whi,
                                 __nv_bfloat16* __restrict__ wlo, int total4)
{
    const int e = blockIdx.x * 256 + threadIdx.x;
    if (e >= total4) return;
    float4 v = ((const float4*)W)[e];
    uint32_t h0, l0, h1, l1;
    split2(v.x, v.y, h0, l0);
    split2(v.z, v.w, h1, l1);
    ((uint2*)whi)[e] = make_uint2(h0, h1);
    ((uint2*)wlo)[e] = make_uint2(l0, l1);
}

// =========================================================================
// 6) bf16x3 GEMM: mma.sync + ldmatrix, cp.async 3-stage pipeline.
//    Block 128m x 64n, BK=32, 8 warps (4m x 2n), warp 32x32.
//    Epilogue accumulates per-channel BN stats via shfl + atomicAdd.
// =========================================================================
template<int K>
__global__ void __launch_bounds__(256) gemm_cp_kernel(
    const __nv_bfloat16* __restrict__ Ahi, const __nv_bfloat16* __restrict__ Alo,
    const float* __restrict__ bias,
    const __nv_bfloat16* __restrict__ Bhi, const __nv_bfloat16* __restrict__ Blo,
    float* __restrict__ Y, float* __restrict__ redS, float* __restrict__ redSS)
{
    constexpr int NT  = K / 32;
    constexpr int ASZ = 128 * 128;
    constexpr int BSZ = 64 * 128;
    constexpr int STG = ASZ + BSZ;   // 24576 per stage

    extern __shared__ __align__(16) unsigned char smem[];
    const uint32_t sb = smem_u32(smem);

    const int tid  = threadIdx.x;
    const int wid  = tid >> 5;
    const int lane = tid & 31;
    const int wm   = wid >> 1;
    const int wn   = wid & 1;

    const int b  = blockIdx.z;
    const int n0 = blockIdx.x * 64;
    const int m0 = blockIdx.y * 128;

    const size_t aoff = (size_t)m0 * K;
    const size_t boff = ((size_t)b * N1 + n0) * K;

    float acc[2][4][4];
    #pragma unroll
    for (int mt = 0; mt < 2; ++mt)
        #pragma unroll
        for (int nt = 0; nt < 4; ++nt)
            #pragma unroll
            for (int e = 0; e < 4; ++e) acc[mt][nt][e] = 0.f;

    auto load_tile = [&](int kt, int s) {
        const int k0 = kt * 32;
        const uint32_t As = sb + s * STG;
        const uint32_t Bs = As + ASZ;
        #pragma unroll
        for (int it = 0; it < 4; ++it) {
            const int idx = tid + it * 256;     // 0..1023
            const int r = idx >> 3, c = idx & 7;
            const __nv_bfloat16* src = (c < 4)
                ? Ahi + aoff + (size_t)r * K + k0 + c * 8
                : Alo + aoff + (size_t)r * K + k0 + (c - 4) * 8;
            CP16(As + swz(r, c), src);
        }
        #pragma unroll
        for (int it = 0; it < 2; ++it) {
            const int idx = tid + it * 256;     // 0..511
            const int r = idx >> 3, c = idx & 7;
            const __nv_bfloat16* src = (c < 4)
                ? Bhi + boff + (size_t)r * K + k0 + c * 8
                : Blo + boff + (size_t)r * K + k0 + (c - 4) * 8;
            CP16(Bs + swz(r, c), src);
        }
    };

    // ldmatrix lane addressing
    const int a_row  = (lane & 7) + ((lane >> 3) & 1) * 8;
    const int a_csel = lane >> 4;
    const int b_row  = lane & 7;
    const int b_sel  = lane >> 3;
    const int b_noff = (b_sel >> 1) * 8;
    const int b_csel = b_sel & 1;

    auto compute = [&](int s) {
        const uint32_t Asb = sb + s * STG;
        const uint32_t Bsb = Asb + ASZ;
        #pragma unroll
        for (int kk = 0; kk < 2; ++kk) {
            uint32_t a_hi[2][4], a_lo[2][4];
            uint32_t b_hi[4][2], b_lo[4][2];
            #pragma unroll
            for (int mt = 0; mt < 2; ++mt) {
                const int row = wm * 32 + mt * 16 + a_row;
                LDSM_X4(a_hi[mt], Asb + swz(row, kk * 2 + a_csel));
                LDSM_X4(a_lo[mt], Asb + swz(row, 4 + kk * 2 + a_csel));
            }
            #pragma unroll
            for (int g = 0; g < 2; ++g) {
                const int row = wn * 32 + g * 16 + b_noff + b_row;
                uint32_t t[4];
                LDSM_X4(t, Bsb + swz(row, kk * 2 + b_csel));
                b_hi[2 * g][0] = t[0]; b_hi[2 * g][1] = t[1];
                b_hi[2 * g + 1][0] = t[2]; b_hi[2 * g + 1][1] = t[3];
                LDSM_X4(t, Bsb + swz(row, 4 + kk * 2 + b_csel));
                b_lo[2 * g][0] = t[0]; b_lo[2 * g][1] = t[1];
                b_lo[2 * g + 1][0] = t[2]; b_lo[2 * g + 1][1] = t[3];
            }
            #pragma unroll
            for (int mt = 0; mt < 2; ++mt)
                #pragma unroll
                for (int nt = 0; nt < 4; ++nt) {
                    MMA16816(acc[mt][nt], a_hi[mt], b_hi[nt][0], b_hi[nt][1]);
                    MMA16816(acc[mt][nt], a_hi[mt], b_lo[nt][0], b_lo[nt][1]);
                    MMA16816(acc[mt][nt], a_lo[mt], b_hi[nt][0], b_hi[nt][1]);
                }
        }
    };

    load_tile(0, 0); CPCOMMIT();
    load_tile(1, 1); CPCOMMIT();

    for (int t = 0; t < NT; ++t) {
        CPWAIT1();
        __syncthreads();
        if (t + 2 < NT) load_tile(t + 2, (t + 2) % 3);
        CPCOMMIT();
        compute(t % 3);
    }

    // ---- epilogue: + bias, store, and accumulate BN stats ----
    const int lw = lane >> 2;
    const int ln = (lane & 3) * 2;
    #pragma unroll
    for (int mt = 0; mt < 2; ++mt) {
        #pragma unroll
        for (int h = 0; h < 2; ++h) {
            const int m = m0 + wm * 32 + mt * 16 + lw + h * 8;
            const float bi = bias[m];
            float* yrow = Y + ((size_t)b * M_OUT + m) * N1 + n0 + wn * 32;
            float s = 0.f, ss = 0.f;
            #pragma unroll
            for (int nt = 0; nt < 4; ++nt) {
                float v0 = acc[mt][nt][h * 2 + 0] + bi;
                float v1 = acc[mt][nt][h * 2 + 1] + bi;
                *(float2*)&yrow[nt * 8 + ln] = make_float2(v0, v1);
                s += v0 + v1;
                ss = fmaf(v0, v0, ss);
                ss = fmaf(v1, v1, ss);
            }
            s  += __shfl_xor_sync(0xffffffff, s, 1);
            ss += __shfl_xor_sync(0xffffffff, ss, 1);
            s  += __shfl_xor_sync(0xffffffff, s, 2);
            ss += __shfl_xor_sync(0xffffffff, ss, 2);
            if ((lane & 3) == 0) {
                atomicAdd(&redS[m], s);
                atomicAdd(&redSS[m], ss);
            }
        }
    }
}

// =========================================================================
// 7) BN finalize: (sum, sumsq) -> scale/shift
// =========================================================================
__global__ void bn_finalize_kernel(const float* __restrict__ gamma,
                                   const float* __restrict__ beta,
                                   const float* __restrict__ S,
                                   const float* __restrict__ SS)
{
    const int o = threadIdx.x;
    const float inv = 1.f / (float)(BB * N1);
    float mu  = S[o] * inv;
    float var = SS[o] * inv - mu * mu;
    float sc  = gamma[o] * rsqrtf(var + 1e-5f);
    g_scale[o] = sc;
    g_shift[o] = fmaf(-mu, sc, beta[o]);
}

// =========================================================================
// 8) BN apply + ReLU (final output only)
// =========================================================================
__global__ void __launch_bounds__(256) bn_apply_kernel(float* __restrict__ Y)
{
    const size_t base = ((size_t)blockIdx.x * 256 + threadIdx.x) * 4;
    if (base >= (size_t)TOT) return;
    const int o = (int)((base / N1) % M_OUT);
    const float sc = g_scale[o];
    const float sf = g_shift[o];
    float4 v = *(float4*)&Y[base];
    v.x = fmaxf(fmaf(v.x, sc, sf), 0.f);
    v.y = fmaxf(fmaf(v.y, sc, sf), 0.f);
    v.z = fmaxf(fmaf(v.z, sc, sf), 0.f);
    v.w = fmaxf(fmaf(v.w, sc, sf), 0.f);
    *(float4*)&Y[base] = v;
}

// =========================================================================
// launcher
// =========================================================================
extern "C" void kernel_launch(void* const* d_in, const int* in_sizes, int n_in,
                              void* d_out, int out_size)
{
    const float* p1  = (const float*)d_in[0];
    const float* x1  = (const float*)d_in[1];
    const float* p2  = (const float*)d_in[2];
    const float* x2  = (const float*)d_in[3];
    const float* W1  = (const float*)d_in[4];
    const float* b1  = (const float*)d_in[5];
    const float* g1  = (const float*)d_in[6];
    const float* be1 = (const float*)d_in[7];
    const float* W2  = (const float*)d_in[8];
    const float* b2  = (const float*)d_in[9];
    const float* g2  = (const float*)d_in[10];
    const float* be2 = (const float*)d_in[11];
    float* out = (float*)d_out;

    float* y1;  cudaGetSymbolAddress((void**)&y1, g_y1);
    float *s1, *ss1, *s2, *ss2;
    cudaGetSymbolAddress((void**)&s1,  g_s1);
    cudaGetSymbolAddress((void**)&ss1, g_ss1);
    cudaGetSymbolAddress((void**)&s2,  g_s2);
    cudaGetSymbolAddress((void**)&ss2, g_ss2);
    __nv_bfloat16 *xb1h, *xb1l, *xb2h, *xb2l, *w1h, *w1l, *w2h, *w2l;
    cudaGetSymbolAddress((void**)&xb1h, g_xb1_hi);
    cudaGetSymbolAddress((void**)&xb1l, g_xb1_lo);
    cudaGetSymbolAddress((void**)&xb2h, g_xb2_hi);
    cudaGetSymbolAddress((void**)&xb2l, g_xb2_lo);
    cudaGetSymbolAddress((void**)&w1h, g_w1_hi);
    cudaGetSymbolAddress((void**)&w1l, g_w1_lo);
    cudaGetSymbolAddress((void**)&w2h, g_w2_hi);
    cudaGetSymbolAddress((void**)&w2l, g_w2_lo);

    const int smem_bytes = 3 * (128 * 128 + 64 * 128);  // 73728
    cudaFuncSetAttribute(gemm_cp_kernel<K1>,
                         cudaFuncAttributeMaxDynamicSharedMemorySize, smem_bytes);
    cudaFuncSetAttribute(gemm_cp_kernel<K2>,
                         cudaFuncAttributeMaxDynamicSharedMemorySize, smem_bytes);

    // 0) zero BN accumulators
    zero_acc_kernel<<<1, M_OUT>>>();
    // 1) KNN
    knn_kernel<<<dim3(N1 / 128, BB), 128>>>(p1, p2);
    // 2) transpose x2
    transpose_x2_kernel<<<dim3(N2 / 32, C2 / 32, BB), dim3(32, 8)>>>(x2);
    // 3) weight conversions (tiny)
    convert_w_kernel<<<(M_OUT * K1 / 4 + 255) / 256, 256>>>(W1, w1h, w1l, M_OUT * K1 / 4);
    convert_w_kernel<<<(M_OUT * K2 / 4 + 255) / 256, 256>>>(W2, w2h, w2l, M_OUT * K2 / 4);
    // 4) B1 planes: x1 part (k<128) + gathered interp part (k in [128,384))
    convert_nmajor_kernel<false><<<dim3(N1 / 32, C1 / 32, BB), dim3(32, 8)>>>(x1, xb1h, xb1l, C1, K1);
    gather_xb1_kernel<<<(BB * N1) / 8, 256>>>();
    // 5) GEMM1 -> y1 fp32 (raw + bias) + BN1 stats
    gemm_cp_kernel<K1><<<dim3(N1 / 64, 2, BB), 256, smem_bytes>>>(w1h, w1l, b1, xb1h, xb1l, y1, s1, ss1);
    // 6) BN1 finalize
    bn_finalize_kernel<<<1, M_OUT>>>(g1, be1, s1, ss1);
    // 7) B2 planes: BN1(y1)+ReLU, transpose-converted
    convert_nmajor_kernel<true><<<dim3(N1 / 32, M_OUT / 32, BB), dim3(32, 8)>>>(y1, xb2h, xb2l, M_OUT, K2);
    // 8) GEMM2 -> out (raw + bias) + BN2 stats
    gemm_cp_kernel<K2><<<dim3(N1 / 64, 2, BB), 256, smem_bytes>>>(w2h, w2l, b2, xb2h, xb2l, out, s2, ss2);
    // 9) BN2 finalize + apply
    bn_finalize_kernel<<<1, M_OUT>>>(g2, be2, s2, ss2);
    bn_apply_kernel<<<TOT / 1024, 256>>>(out);
}

// round 16
// speedup vs baseline: 1.0302x; 1.0302x over previous
#include <cuda_runtime.h>
#include <cuda_bf16.h>
#include <cstdint>
#include <math.h>
#include <float.h>

// Problem constants
#define BB 2
#define N1 16384
#define N2 4096
#define C1 128
#define C2 256
#define M_OUT 256
#define K1 384
#define K2 256
#define TOT (BB * M_OUT * N1)

// ---------------- device scratch ----------------
__device__ float g_x2t[BB * N2 * C2];       // x2 transposed (B, N2, C2)
__device__ int   g_idx[BB * N1 * 3];
__device__ float g_w[BB * N1 * 3];
__device__ float g_y1[BB * M_OUT * N1];     // (B, 256, N1) n-contig fp32
__device__ float g_scale[M_OUT];
__device__ float g_shift[M_OUT];
__device__ float g_s1[M_OUT], g_ss1[M_OUT]; // BN1 accumulators
__device__ float g_s2[M_OUT], g_ss2[M_OUT]; // BN2 accumulators

// Pre-converted bf16 hi/lo operand planes (k-contig rows)
__device__ __nv_bfloat16 g_xb1_hi[BB * N1 * K1];
__device__ __nv_bfloat16 g_xb1_lo[BB * N1 * K1];
__device__ __nv_bfloat16 g_xb2_hi[BB * N1 * K2];
__device__ __nv_bfloat16 g_xb2_lo[BB * N1 * K2];
__device__ __nv_bfloat16 g_w1_hi[M_OUT * K1];
__device__ __nv_bfloat16 g_w1_lo[M_OUT * K1];
__device__ __nv_bfloat16 g_w2_hi[M_OUT * K2];
__device__ __nv_bfloat16 g_w2_lo[M_OUT * K2];

// ---------------- helpers ----------------
__device__ __forceinline__ uint32_t smem_u32(const void* p) {
    uint32_t a;
    asm("{ .reg .u64 t; cvta.to.shared.u64 t, %1; cvt.u32.u64 %0, t; }" : "=r"(a) : "l"(p));
    return a;
}
#define LDSM_X4(R, ADDR) \
    asm volatile("ldmatrix.sync.aligned.m8n8.x4.shared.b16 {%0,%1,%2,%3}, [%4];" \
        : "=r"((R)[0]), "=r"((R)[1]), "=r"((R)[2]), "=r"((R)[3]) : "r"(ADDR))
#define MMA16816(C, A, B0, B1) \
    asm volatile("mma.sync.aligned.m16n8k16.row.col.f32.bf16.bf16.f32 " \
        "{%0,%1,%2,%3}, {%4,%5,%6,%7}, {%8,%9}, {%0,%1,%2,%3};" \
        : "+f"((C)[0]), "+f"((C)[1]), "+f"((C)[2]), "+f"((C)[3]) \
        : "r"((A)[0]), "r"((A)[1]), "r"((A)[2]), "r"((A)[3]), "r"(B0), "r"(B1))
#define CP16(dst, src) \
    asm volatile("cp.async.cg.shared.global [%0], [%1], 16;" :: "r"(dst), "l"(src))
#define CPCOMMIT() asm volatile("cp.async.commit_group;" ::: "memory")
#define CPWAIT1()  asm volatile("cp.async.wait_group 1;" ::: "memory")

// packed f32x2 ops (each lane = independent .rn op, bit-exact vs scalar)
#define MUL2(D, A, B)    asm("mul.rn.f32x2 %0, %1, %2;"     : "=l"(D) : "l"(A), "l"(B))
#define FMA2V(D, A, B, C) asm("fma.rn.f32x2 %0, %1, %2, %3;" : "=l"(D) : "l"(A), "l"(B), "l"(C))
#define ADD2(D, A, B)    asm("add.rn.f32x2 %0, %1, %2;"     : "=l"(D) : "l"(A), "l"(B))
#define DUPP(D, S)       asm("mov.b64 %0, {%1, %1};"        : "=l"(D) : "f"(S))
#define UNPK(LO, HI, S)  asm("mov.b64 {%0, %1}, %2;"        : "=f"(LO), "=f"(HI) : "l"(S))

__device__ __forceinline__ void split1(float x, __nv_bfloat16& hi, __nv_bfloat16& lo) {
    hi = __float2bfloat16(x);
    lo = __float2bfloat16(x - __bfloat162float(hi));
}
__device__ __forceinline__ void split2(float x, float y, uint32_t& hi, uint32_t& lo) {
    __nv_bfloat16 hx, lx, hy, ly;
    split1(x, hx, lx); split1(y, hy, ly);
    hi = ((uint32_t)__bfloat16_as_ushort(hy) << 16) | __bfloat16_as_ushort(hx);
    lo = ((uint32_t)__bfloat16_as_ushort(ly) << 16) | __bfloat16_as_ushort(lx);
}
// smem offset: row*128 B, 8 chunks of 16 B, chunk ^= row&7 (XOR swizzle)
__device__ __forceinline__ uint32_t swz(int row, int chunk) {
    return (uint32_t)(row * 128 + ((chunk ^ (row & 7)) << 4));
}

// =========================================================================
// 0) Zero BN accumulators (graph-safe, runs every launch)
// =========================================================================
__global__ void zero_acc_kernel()
{
    const int t = threadIdx.x;
    g_s1[t] = 0.f; g_ss1[t] = 0.f;
    g_s2[t] = 0.f; g_ss2[t] = 0.f;
}

// =========================================================================
// 1) KNN — reference-exact distance arithmetic, f32x2-packed (R13 version)
// =========================================================================
#define KNN_CHUNK 2048

__global__ void __launch_bounds__(128) knn_kernel(const float* __restrict__ p1,
                                                  const float* __restrict__ p2)
{
    __shared__ ulonglong2 s_xy[KNN_CHUNK / 2];   // {x01, y01}
    __shared__ ulonglong2 s_zb[KNN_CHUNK / 2];   // {z01, bb01}

    const int b = blockIdx.y;
    const int n = blockIdx.x * 128 + threadIdx.x;

    const size_t qoff = ((size_t)b * N1 + n) * 3;
    const float qx = p1[qoff + 0];
    const float qy = p1[qoff + 1];
    const float qz = p1[qoff + 2];
    float tq = __fadd_rn(__fmul_rn(qx, qx), __fmul_rn(qy, qy));
    const float qq = __fadd_rn(tq, __fmul_rn(qz, qz));

    unsigned long long qx2, qy2, qz2, qq2, neg2;
    DUPP(qx2, qx); DUPP(qy2, qy); DUPP(qz2, qz); DUPP(qq2, qq);
    DUPP(neg2, -2.0f);

    float d0 = FLT_MAX, d1 = FLT_MAX, d2 = FLT_MAX;
    int   i0 = 0,       i1 = 0,       i2 = 0;

    const float* p2b = p2 + (size_t)b * N2 * 3;

    #pragma unroll
    for (int chunk = 0; chunk < N2 / KNN_CHUNK; ++chunk) {
        if (chunk > 0) __syncthreads();
        const int jbase = chunk * KNN_CHUNK;
        for (int jp = threadIdx.x; jp < KNN_CHUNK / 2; jp += 128) {
            const float* r = p2b + (jbase + jp * 2) * 3;
            float x0 = r[0], y0 = r[1], z0 = r[2];
            float x1 = r[3], y1 = r[4], z1 = r[5];
            float b0 = __fadd_rn(__fadd_rn(__fmul_rn(x0, x0), __fmul_rn(y0, y0)), __fmul_rn(z0, z0));
            float b1 = __fadd_rn(__fadd_rn(__fmul_rn(x1, x1), __fmul_rn(y1, y1)), __fmul_rn(z1, z1));
            *(float2*)&s_xy[jp].x = make_float2(x0, x1);
            *(float2*)&s_xy[jp].y = make_float2(y0, y1);
            *(float2*)&s_zb[jp].x = make_float2(z0, z1);
            *(float2*)&s_zb[jp].y = make_float2(b0, b1);
        }
        __syncthreads();

        #pragma unroll 4
        for (int jp = 0; jp < KNN_CHUNK / 2; ++jp) {
            ulonglong2 xy = s_xy[jp];
            ulonglong2 zb = s_zb[jp];
            unsigned long long dot, s, m2, dp;
            MUL2(dot, qx2, xy.x);
            FMA2V(dot, qy2, xy.y, dot);
            FMA2V(dot, qz2, zb.x, dot);
            ADD2(s, qq2, zb.y);
            MUL2(m2, dot, neg2);
            ADD2(dp, s, m2);
            float dl, dh;
            UNPK(dl, dh, dp);
            if (dl < d2) {
                const int jg = jbase + jp * 2;
                if (dl < d1) {
                    d2 = d1; i2 = i1;
                    if (dl < d0) { d1 = d0; i1 = i0; d0 = dl; i0 = jg; }
                    else         { d1 = dl; i1 = jg; }
                } else { d2 = dl; i2 = jg; }
            }
            if (dh < d2) {
                const int jg = jbase + jp * 2 + 1;
                if (dh < d1) {
                    d2 = d1; i2 = i1;
                    if (dh < d0) { d1 = d0; i1 = i0; d0 = dh; i0 = jg; }
                    else         { d1 = dh; i1 = jg; }
                } else { d2 = dh; i2 = jg; }
            }
        }
    }

    d0 = fmaxf(d0, 0.0f);
    d1 = fmaxf(d1, 0.0f);
    d2 = fmaxf(d2, 0.0f);
    float w0 = 1.f / (d0 + 1e-16f);
    float w1 = 1.f / (d1 + 1e-16f);
    float w2 = 1.f / (d2 + 1e-16f);
    float ws = 1.f / (w0 + w1 + w2);

    const int base = (b * N1 + n) * 3;
    g_w[base + 0] = w0 * ws;
    g_w[base + 1] = w1 * ws;
    g_w[base + 2] = w2 * ws;
    g_idx[base + 0] = i0;
    g_idx[base + 1] = i1;
    g_idx[base + 2] = i2;
}

// =========================================================================
// 2) Transpose x2 (B, C2, N2) -> (B, N2, C2)
// =========================================================================
__global__ void transpose_x2_kernel(const float* __restrict__ x2)
{
    __shared__ float tile[32][33];
    const int b  = blockIdx.z;
    const int c0 = blockIdx.y * 32;
    const int n0 = blockIdx.x * 32;
    const int tx = threadIdx.x;
    const int ty = threadIdx.y;

    #pragma unroll
    for (int i = ty; i < 32; i += 8)
        tile[i][tx] = x2[((size_t)b * C2 + c0 + i) * N2 + n0 + tx];
    __syncthreads();
    #pragma unroll
    for (int i = ty; i < 32; i += 8)
        g_x2t[((size_t)b * N2 + n0 + i) * C2 + c0 + tx] = tile[tx][i];
}

// =========================================================================
// 3) Gather + interpolate -> bf16 hi/lo planes of GEMM1 B (k in [128,384))
//    float4 loads, uint2 stores
// =========================================================================
__global__ void __launch_bounds__(256) gather_xb1_kernel()
{
    const int q    = blockIdx.x * 8 + (threadIdx.x >> 5);
    const int lane = threadIdx.x & 31;
    const int b = q / N1;
    const int n = q % N1;

    const int base = q * 3;
    const float w0 = g_w[base + 0];
    const float w1 = g_w[base + 1];
    const float w2 = g_w[base + 2];
    const float* f0 = g_x2t + ((size_t)b * N2 + g_idx[base + 0]) * C2;
    const float* f1 = g_x2t + ((size_t)b * N2 + g_idx[base + 1]) * C2;
    const float* f2 = g_x2t + ((size_t)b * N2 + g_idx[base + 2]) * C2;
    const size_t obase = ((size_t)b * N1 + n) * K1 + C1;

    #pragma unroll
    for (int it = 0; it < 2; ++it) {
        const int c = it * 128 + lane * 4;
        float4 a0 = *(const float4*)&f0[c];
        float4 a1 = *(const float4*)&f1[c];
        float4 a2 = *(const float4*)&f2[c];
        float v0 = fmaf(w0, a0.x, fmaf(w1, a1.x, w2 * a2.x));
        float v1 = fmaf(w0, a0.y, fmaf(w1, a1.y, w2 * a2.y));
        float v2 = fmaf(w0, a0.z, fmaf(w1, a1.z, w2 * a2.z));
        float v3 = fmaf(w0, a0.w, fmaf(w1, a1.w, w2 * a2.w));
        uint32_t h0, l0, h1, l1;
        split2(v0, v1, h0, l0);
        split2(v2, v3, h1, l1);
        *(uint2*)&g_xb1_hi[obase + c] = make_uint2(h0, h1);
        *(uint2*)&g_xb1_lo[obase + c] = make_uint2(l0, l1);
    }
}

// =========================================================================
// 4) Transpose-convert n-major fp32 -> k-contig bf16 hi/lo planes
//    phase 2 uses all 256 threads (4 k-values each, uint2 stores)
// =========================================================================
template<bool BN>
__global__ void convert_nmajor_kernel(const float* __restrict__ src,
                                      __nv_bfloat16* __restrict__ dhi,
                                      __nv_bfloat16* __restrict__ dlo,
                                      int C, int Kdst)
{
    __shared__ float tile[32][33];
    const int b  = blockIdx.z;
    const int c0 = blockIdx.y * 32;
    const int n0 = blockIdx.x * 32;
    const int tx = threadIdx.x;   // 32
    const int ty = threadIdx.y;   // 8

    #pragma unroll
    for (int i = ty; i < 32; i += 8) {
        float v = src[((size_t)b * C + c0 + i) * N1 + n0 + tx];
        if (BN) v = fmaxf(fmaf(v, g_scale[c0 + i], g_shift[c0 + i]), 0.f);
        tile[i][tx] = v;
    }
    __syncthreads();

    const int tid = ty * 32 + tx;
    const int r = tid >> 3;   // n row 0..31
    const int q = tid & 7;    // 4-k chunk 0..7
    uint32_t h0, l0, h1, l1;
    split2(tile[q * 4 + 0][r], tile[q * 4 + 1][r], h0, l0);
    split2(tile[q * 4 + 2][r], tile[q * 4 + 3][r], h1, l1);
    const size_t o = ((size_t)b * N1 + n0 + r) * Kdst + c0 + q * 4;
    *(uint2*)&dhi[o] = make_uint2(h0, h1);
    *(uint2*)&dlo[o] = make_uint2(l0, l1);
}

// =========================================================================
// 5) Convert W fp32 -> bf16 hi/lo (flat)
// =========================================================================
__global__ void convert_w_kernel(const float* __restrict__ W,
                                 __nv_bfloat16* __restrict__ whi,
                                 __nv_bfloat16* __restrict__ wlo, int total4)
{
    const int e = blockIdx.x * 256 + threadIdx.x;
    if (e >= total4) return;
    float4 v = ((const float4*)W)[e];
    uint32_t h0, l0, h1, l1;
    split2(v.x, v.y, h0, l0);
    split2(v.z, v.w, h1, l1);
    ((uint2*)whi)[e] = make_uint2(h0, h1);
    ((uint2*)wlo)[e] = make_uint2(l0, l1);
}

// =========================================================================
// 6) bf16x3 GEMM: mma.sync + ldmatrix, cp.async 3-stage pipeline.
//    Block 128m x 64n, BK=32, 8 warps (4m x 2n), warp 32x32.
//    Epilogue accumulates per-channel BN stats via shfl + atomicAdd.
// =========================================================================
template<int K>
__global__ void __launch_bounds__(256) gemm_cp_kernel(
    const __nv_bfloat16* __restrict__ Ahi, const __nv_bfloat16* __restrict__ Alo,
    const float* __restrict__ bias,
    const __nv_bfloat16* __restrict__ Bhi, const __nv_bfloat16* __restrict__ Blo,
    float* __restrict__ Y, float* __restrict__ redS, float* __restrict__ redSS)
{
    constexpr int NT  = K / 32;
    constexpr int ASZ = 128 * 128;
    constexpr int BSZ = 64 * 128;
    constexpr int STG = ASZ + BSZ;   // 24576 per stage

    extern __shared__ __align__(16) unsigned char smem[];
    const uint32_t sb = smem_u32(smem);

    const int tid  = threadIdx.x;
    const int wid  = tid >> 5;
    const int lane = tid & 31;
    const int wm   = wid >> 1;
    const int wn   = wid & 1;

    const int b  = blockIdx.z;
    const int n0 = blockIdx.x * 64;
    const int m0 = blockIdx.y * 128;

    const size_t aoff = (size_t)m0 * K;
    const size_t boff = ((size_t)b * N1 + n0) * K;

    float acc[2][4][4];
    #pragma unroll
    for (int mt = 0; mt < 2; ++mt)
        #pragma unroll
        for (int nt = 0; nt < 4; ++nt)
            #pragma unroll
            for (int e = 0; e < 4; ++e) acc[mt][nt][e] = 0.f;

    auto load_tile = [&](int kt, int s) {
        const int k0 = kt * 32;
        const uint32_t As = sb + s * STG;
        const uint32_t Bs = As + ASZ;
        #pragma unroll
        for (int it = 0; it < 4; ++it) {
            const int idx = tid + it * 256;     // 0..1023
            const int r = idx >> 3, c = idx & 7;
            const __nv_bfloat16* src = (c < 4)
                ? Ahi + aoff + (size_t)r * K + k0 + c * 8
                : Alo + aoff + (size_t)r * K + k0 + (c - 4) * 8;
            CP16(As + swz(r, c), src);
        }
        #pragma unroll
        for (int it = 0; it < 2; ++it) {
            const int idx = tid + it * 256;     // 0..511
            const int r = idx >> 3, c = idx & 7;
            const __nv_bfloat16* src = (c < 4)
                ? Bhi + boff + (size_t)r * K + k0 + c * 8
                : Blo + boff + (size_t)r * K + k0 + (c - 4) * 8;
            CP16(Bs + swz(r, c), src);
        }
    };

    // ldmatrix lane addressing
    const int a_row  = (lane & 7) + ((lane >> 3) & 1) * 8;
    const int a_csel = lane >> 4;
    const int b_row  = lane & 7;
    const int b_sel  = lane >> 3;
    const int b_noff = (b_sel >> 1) * 8;
    const int b_csel = b_sel & 1;

    auto compute = [&](int s) {
        const uint32_t Asb = sb + s * STG;
        const uint32_t Bsb = Asb + ASZ;
        #pragma unroll
        for (int kk = 0; kk < 2; ++kk) {
            uint32_t a_hi[2][4], a_lo[2][4];
            uint32_t b_hi[4][2], b_lo[4][2];
            #pragma unroll
            for (int mt = 0; mt < 2; ++mt) {
                const int row = wm * 32 + mt * 16 + a_row;
                LDSM_X4(a_hi[mt], Asb + swz(row, kk * 2 + a_csel));
                LDSM_X4(a_lo[mt], Asb + swz(row, 4 + kk * 2 + a_csel));
            }
            #pragma unroll
            for (int g = 0; g < 2; ++g) {
                const int row = wn * 32 + g * 16 + b_noff + b_row;
                uint32_t t[4];
                LDSM_X4(t, Bsb + swz(row, kk * 2 + b_csel));
                b_hi[2 * g][0] = t[0]; b_hi[2 * g][1] = t[1];
                b_hi[2 * g + 1][0] = t[2]; b_hi[2 * g + 1][1] = t[3];
                LDSM_X4(t, Bsb + swz(row, 4 + kk * 2 + b_csel));
                b_lo[2 * g][0] = t[0]; b_lo[2 * g][1] = t[1];
                b_lo[2 * g + 1][0] = t[2]; b_lo[2 * g + 1][1] = t[3];
            }
            #pragma unroll
            for (int mt = 0; mt < 2; ++mt)
                #pragma unroll
                for (int nt = 0; nt < 4; ++nt) {
                    MMA16816(acc[mt][nt], a_hi[mt], b_hi[nt][0], b_hi[nt][1]);
                    MMA16816(acc[mt][nt], a_hi[mt], b_lo[nt][0], b_lo[nt][1]);
                    MMA16816(acc[mt][nt], a_lo[mt], b_hi[nt][0], b_hi[nt][1]);
                }
        }
    };

    load_tile(0, 0); CPCOMMIT();
    load_tile(1, 1); CPCOMMIT();

    for (int t = 0; t < NT; ++t) {
        CPWAIT1();
        __syncthreads();
        if (t + 2 < NT) load_tile(t + 2, (t + 2) % 3);
        CPCOMMIT();
        compute(t % 3);
    }

    // ---- epilogue: + bias, store, and accumulate BN stats ----
    const int lw = lane >> 2;
    const int ln = (lane & 3) * 2;
    #pragma unroll
    for (int mt = 0; mt < 2; ++mt) {
        #pragma unroll
        for (int h = 0; h < 2; ++h) {
            const int m = m0 + wm * 32 + mt * 16 + lw + h * 8;
            const float bi = bias[m];
            float* yrow = Y + ((size_t)b * M_OUT + m) * N1 + n0 + wn * 32;
            float s = 0.f, ss = 0.f;
            #pragma unroll
            for (int nt = 0; nt < 4; ++nt) {
                float v0 = acc[mt][nt][h * 2 + 0] + bi;
                float v1 = acc[mt][nt][h * 2 + 1] + bi;
                *(float2*)&yrow[nt * 8 + ln] = make_float2(v0, v1);
                s += v0 + v1;
                ss = fmaf(v0, v0, ss);
                ss = fmaf(v1, v1, ss);
            }
            s  += __shfl_xor_sync(0xffffffff, s, 1);
            ss += __shfl_xor_sync(0xffffffff, ss, 1);
            s  += __shfl_xor_sync(0xffffffff, s, 2);
            ss += __shfl_xor_sync(0xffffffff, ss, 2);
            if ((lane & 3) == 0) {
                atomicAdd(&redS[m], s);
                atomicAdd(&redSS[m], ss);
            }
        }
    }
}

// =========================================================================
// 7) BN finalize: (sum, sumsq) -> scale/shift
// =========================================================================
__global__ void bn_finalize_kernel(const float* __restrict__ gamma,
                                   const float* __restrict__ beta,
                                   const float* __restrict__ S,
                                   const float* __restrict__ SS)
{
    const int o = threadIdx.x;
    const float inv = 1.f / (float)(BB * N1);
    float mu  = S[o] * inv;
    float var = SS[o] * inv - mu * mu;
    float sc  = gamma[o] * rsqrtf(var + 1e-5f);
    g_scale[o] = sc;
    g_shift[o] = fmaf(-mu, sc, beta[o]);
}

// =========================================================================
// 8) BN apply + ReLU (final output only)
// =========================================================================
__global__ void __launch_bounds__(256) bn_apply_kernel(float* __restrict__ Y)
{
    const size_t base = ((size_t)blockIdx.x * 256 + threadIdx.x) * 4;
    if (base >= (size_t)TOT) return;
    const int o = (int)((base / N1) % M_OUT);
    const float sc = g_scale[o];
    const float sf = g_shift[o];
    float4 v = *(float4*)&Y[base];
    v.x = fmaxf(fmaf(v.x, sc, sf), 0.f);
    v.y = fmaxf(fmaf(v.y, sc, sf), 0.f);
    v.z = fmaxf(fmaf(v.z, sc, sf), 0.f);
    v.w = fmaxf(fmaf(v.w, sc, sf), 0.f);
    *(float4*)&Y[base] = v;
}

// =========================================================================
// launcher
// =========================================================================
extern "C" void kernel_launch(void* const* d_in, const int* in_sizes, int n_in,
                              void* d_out, int out_size)
{
    const float* p1  = (const float*)d_in[0];
    const float* x1  = (const float*)d_in[1];
    const float* p2  = (const float*)d_in[2];
    const float* x2  = (const float*)d_in[3];
    const float* W1  = (const float*)d_in[4];
    const float* b1  = (const float*)d_in[5];
    const float* g1  = (const float*)d_in[6];
    const float* be1 = (const float*)d_in[7];
    const float* W2  = (const float*)d_in[8];
    const float* b2  = (const float*)d_in[9];
    const float* g2  = (const float*)d_in[10];
    const float* be2 = (const float*)d_in[11];
    float* out = (float*)d_out;

    float* y1;  cudaGetSymbolAddress((void**)&y1, g_y1);
    float *s1, *ss1, *s2, *ss2;
    cudaGetSymbolAddress((void**)&s1,  g_s1);
    cudaGetSymbolAddress((void**)&ss1, g_ss1);
    cudaGetSymbolAddress((void**)&s2,  g_s2);
    cudaGetSymbolAddress((void**)&ss2, g_ss2);
    __nv_bfloat16 *xb1h, *xb1l, *xb2h, *xb2l, *w1h, *w1l, *w2h, *w2l;
    cudaGetSymbolAddress((void**)&xb1h, g_xb1_hi);
    cudaGetSymbolAddress((void**)&xb1l, g_xb1_lo);
    cudaGetSymbolAddress((void**)&xb2h, g_xb2_hi);
    cudaGetSymbolAddress((void**)&xb2l, g_xb2_lo);
    cudaGetSymbolAddress((void**)&w1h, g_w1_hi);
    cudaGetSymbolAddress((void**)&w1l, g_w1_lo);
    cudaGetSymbolAddress((void**)&w2h, g_w2_hi);
    cudaGetSymbolAddress((void**)&w2l, g_w2_lo);

    const int smem_bytes = 3 * (128 * 128 + 64 * 128);  // 73728
    cudaFuncSetAttribute(gemm_cp_kernel<K1>,
                         cudaFuncAttributeMaxDynamicSharedMemorySize, smem_bytes);
    cudaFuncSetAttribute(gemm_cp_kernel<K2>,
                         cudaFuncAttributeMaxDynamicSharedMemorySize, smem_bytes);

    // 0) zero BN accumulators
    zero_acc_kernel<<<1, M_OUT>>>();
    // 1) KNN
    knn_kernel<<<dim3(N1 / 128, BB), 128>>>(p1, p2);
    // 2) transpose x2
    transpose_x2_kernel<<<dim3(N2 / 32, C2 / 32, BB), dim3(32, 8)>>>(x2);
    // 3) weight conversions (tiny)
    convert_w_kernel<<<(M_OUT * K1 / 4 + 255) / 256, 256>>>(W1, w1h, w1l, M_OUT * K1 / 4);
    convert_w_kernel<<<(M_OUT * K2 / 4 + 255) / 256, 256>>>(W2, w2h, w2l, M_OUT * K2 / 4);
    // 4) B1 planes: x1 part (k<128) + gathered interp part (k in [128,384))
    convert_nmajor_kernel<false><<<dim3(N1 / 32, C1 / 32, BB), dim3(32, 8)>>>(x1, xb1h, xb1l, C1, K1);
    gather_xb1_kernel<<<(BB * N1) / 8, 256>>>();
    // 5) GEMM1 -> y1 fp32 (raw + bias) + BN1 stats
    gemm_cp_kernel<K1><<<dim3(N1 / 64, 2, BB), 256, smem_bytes>>>(w1h, w1l, b1, xb1h, xb1l, y1, s1, ss1);
    // 6) BN1 finalize
    bn_finalize_kernel<<<1, M_OUT>>>(g1, be1, s1, ss1);
    // 7) B2 planes: BN1(y1)+ReLU, transpose-converted
    convert_nmajor_kernel<true><<<dim3(N1 / 32, M_OUT / 32, BB), dim3(32, 8)>>>(y1, xb2h, xb2l, M_OUT, K2);
    // 8) GEMM2 -> out (raw + bias) + BN2 stats
    gemm_cp_kernel<K2><<<dim3(N1 / 64, 2, BB), 256, smem_bytes>>>(w2h, w2l, b2, xb2h, xb2l, out, s2, ss2);
    // 9) BN2 finalize + apply
    bn_finalize_kernel<<<1, M_OUT>>>(g2, be2, s2, ss2);
    bn_apply_kernel<<<TOT / 1024, 256>>>(out);
}

// round 17
// speedup vs baseline: 1.0429x; 1.0123x over previous
#include <cuda_runtime.h>
#include <cuda_bf16.h>
#include <cstdint>
#include <math.h>
#include <float.h>

// Problem constants
#define BB 2
#define N1 16384
#define N2 4096
#define C1 128
#define C2 256
#define M_OUT 256
#define K1 384
#define K2 256
#define TOT (BB * M_OUT * N1)

// ---------------- device scratch ----------------
__device__ float g_x2t[BB * N2 * C2];       // x2 transposed (B, N2, C2)
__device__ int   g_idx[BB * N1 * 3];
__device__ float g_w[BB * N1 * 3];
__device__ float g_y1[BB * M_OUT * N1];     // (B, 256, N1) n-contig fp32
__device__ float g_scale[M_OUT];
__device__ float g_shift[M_OUT];
__device__ float g_s1[M_OUT], g_ss1[M_OUT]; // BN1 accumulators
__device__ float g_s2[M_OUT], g_ss2[M_OUT]; // BN2 accumulators

// Pre-converted bf16 hi/lo operand planes (k-contig rows)
__device__ __nv_bfloat16 g_xb1_hi[BB * N1 * K1];
__device__ __nv_bfloat16 g_xb1_lo[BB * N1 * K1];
__device__ __nv_bfloat16 g_xb2_hi[BB * N1 * K2];
__device__ __nv_bfloat16 g_xb2_lo[BB * N1 * K2];
__device__ __nv_bfloat16 g_w1_hi[M_OUT * K1];
__device__ __nv_bfloat16 g_w1_lo[M_OUT * K1];
__device__ __nv_bfloat16 g_w2_hi[M_OUT * K2];
__device__ __nv_bfloat16 g_w2_lo[M_OUT * K2];

// ---------------- helpers ----------------
__device__ __forceinline__ uint32_t smem_u32(const void* p) {
    uint32_t a;
    asm("{ .reg .u64 t; cvta.to.shared.u64 t, %1; cvt.u32.u64 %0, t; }" : "=r"(a) : "l"(p));
    return a;
}
#define LDSM_X4(R, ADDR) \
    asm volatile("ldmatrix.sync.aligned.m8n8.x4.shared.b16 {%0,%1,%2,%3}, [%4];" \
        : "=r"((R)[0]), "=r"((R)[1]), "=r"((R)[2]), "=r"((R)[3]) : "r"(ADDR))
#define MMA16816(C, A, B0, B1) \
    asm volatile("mma.sync.aligned.m16n8k16.row.col.f32.bf16.bf16.f32 " \
        "{%0,%1,%2,%3}, {%4,%5,%6,%7}, {%8,%9}, {%0,%1,%2,%3};" \
        : "+f"((C)[0]), "+f"((C)[1]), "+f"((C)[2]), "+f"((C)[3]) \
        : "r"((A)[0]), "r"((A)[1]), "r"((A)[2]), "r"((A)[3]), "r"(B0), "r"(B1))
#define CP16(dst, src) \
    asm volatile("cp.async.cg.shared.global [%0], [%1], 16;" :: "r"(dst), "l"(src))
#define CPCOMMIT() asm volatile("cp.async.commit_group;" ::: "memory")
#define CPWAIT1()  asm volatile("cp.async.wait_group 1;" ::: "memory")

// packed f32x2 ops (each lane = independent .rn op, bit-exact vs scalar)
#define MUL2(D, A, B)    asm("mul.rn.f32x2 %0, %1, %2;"     : "=l"(D) : "l"(A), "l"(B))
#define FMA2V(D, A, B, C) asm("fma.rn.f32x2 %0, %1, %2, %3;" : "=l"(D) : "l"(A), "l"(B), "l"(C))
#define ADD2(D, A, B)    asm("add.rn.f32x2 %0, %1, %2;"     : "=l"(D) : "l"(A), "l"(B))
#define DUPP(D, S)       asm("mov.b64 %0, {%1, %1};"        : "=l"(D) : "f"(S))
#define UNPK(LO, HI, S)  asm("mov.b64 {%0, %1}, %2;"        : "=f"(LO), "=f"(HI) : "l"(S))

__device__ __forceinline__ void split1(float x, __nv_bfloat16& hi, __nv_bfloat16& lo) {
    hi = __float2bfloat16(x);
    lo = __float2bfloat16(x - __bfloat162float(hi));
}
__device__ __forceinline__ void split2(float x, float y, uint32_t& hi, uint32_t& lo) {
    __nv_bfloat16 hx, lx, hy, ly;
    split1(x, hx, lx); split1(y, hy, ly);
    hi = ((uint32_t)__bfloat16_as_ushort(hy) << 16) | __bfloat16_as_ushort(hx);
    lo = ((uint32_t)__bfloat16_as_ushort(ly) << 16) | __bfloat16_as_ushort(lx);
}
// smem offset: row*128 B, 8 chunks of 16 B, chunk ^= row&7 (XOR swizzle)
__device__ __forceinline__ uint32_t swz(int row, int chunk) {
    return (uint32_t)(row * 128 + ((chunk ^ (row & 7)) << 4));
}

// =========================================================================
// 1) KNN — reference-exact distance arithmetic, f32x2-packed.
//    Block (0,0) additionally zeros the BN accumulators (graph-safe,
//    deterministic; KNN precedes both GEMMs in program order).
// =========================================================================
#define KNN_CHUNK 2048

__global__ void __launch_bounds__(128) knn_kernel(const float* __restrict__ p1,
                                                  const float* __restrict__ p2)
{
    __shared__ ulonglong2 s_xy[KNN_CHUNK / 2];   // {x01, y01}
    __shared__ ulonglong2 s_zb[KNN_CHUNK / 2];   // {z01, bb01}

    const int b = blockIdx.y;
    const int n = blockIdx.x * 128 + threadIdx.x;

    if (blockIdx.x == 0 && blockIdx.y == 0) {
        const int t = threadIdx.x;
        g_s1[t] = 0.f; g_ss1[t] = 0.f; g_s2[t] = 0.f; g_ss2[t] = 0.f;
        g_s1[t + 128] = 0.f; g_ss1[t + 128] = 0.f;
        g_s2[t + 128] = 0.f; g_ss2[t + 128] = 0.f;
    }

    const size_t qoff = ((size_t)b * N1 + n) * 3;
    const float qx = p1[qoff + 0];
    const float qy = p1[qoff + 1];
    const float qz = p1[qoff + 2];
    float tq = __fadd_rn(__fmul_rn(qx, qx), __fmul_rn(qy, qy));
    const float qq = __fadd_rn(tq, __fmul_rn(qz, qz));

    unsigned long long qx2, qy2, qz2, qq2, neg2;
    DUPP(qx2, qx); DUPP(qy2, qy); DUPP(qz2, qz); DUPP(qq2, qq);
    DUPP(neg2, -2.0f);

    float d0 = FLT_MAX, d1 = FLT_MAX, d2 = FLT_MAX;
    int   i0 = 0,       i1 = 0,       i2 = 0;

    const float* p2b = p2 + (size_t)b * N2 * 3;

    #pragma unroll
    for (int chunk = 0; chunk < N2 / KNN_CHUNK; ++chunk) {
        if (chunk > 0) __syncthreads();
        const int jbase = chunk * KNN_CHUNK;
        for (int jp = threadIdx.x; jp < KNN_CHUNK / 2; jp += 128) {
            const float* r = p2b + (jbase + jp * 2) * 3;
            float x0 = r[0], y0 = r[1], z0 = r[2];
            float x1 = r[3], y1 = r[4], z1 = r[5];
            float b0 = __fadd_rn(__fadd_rn(__fmul_rn(x0, x0), __fmul_rn(y0, y0)), __fmul_rn(z0, z0));
            float b1 = __fadd_rn(__fadd_rn(__fmul_rn(x1, x1), __fmul_rn(y1, y1)), __fmul_rn(z1, z1));
            *(float2*)&s_xy[jp].x = make_float2(x0, x1);
            *(float2*)&s_xy[jp].y = make_float2(y0, y1);
            *(float2*)&s_zb[jp].x = make_float2(z0, z1);
            *(float2*)&s_zb[jp].y = make_float2(b0, b1);
        }
        __syncthreads();

        #pragma unroll 4
        for (int jp = 0; jp < KNN_CHUNK / 2; ++jp) {
            ulonglong2 xy = s_xy[jp];
            ulonglong2 zb = s_zb[jp];
            unsigned long long dot, s, m2, dp;
            MUL2(dot, qx2, xy.x);
            FMA2V(dot, qy2, xy.y, dot);
            FMA2V(dot, qz2, zb.x, dot);
            ADD2(s, qq2, zb.y);
            MUL2(m2, dot, neg2);
            ADD2(dp, s, m2);
            float dl, dh;
            UNPK(dl, dh, dp);
            if (dl < d2) {
                const int jg = jbase + jp * 2;
                if (dl < d1) {
                    d2 = d1; i2 = i1;
                    if (dl < d0) { d1 = d0; i1 = i0; d0 = dl; i0 = jg; }
                    else         { d1 = dl; i1 = jg; }
                } else { d2 = dl; i2 = jg; }
            }
            if (dh < d2) {
                const int jg = jbase + jp * 2 + 1;
                if (dh < d1) {
                    d2 = d1; i2 = i1;
                    if (dh < d0) { d1 = d0; i1 = i0; d0 = dh; i0 = jg; }
                    else         { d1 = dh; i1 = jg; }
                } else { d2 = dh; i2 = jg; }
            }
        }
    }

    d0 = fmaxf(d0, 0.0f);
    d1 = fmaxf(d1, 0.0f);
    d2 = fmaxf(d2, 0.0f);
    float w0 = 1.f / (d0 + 1e-16f);
    float w1 = 1.f / (d1 + 1e-16f);
    float w2 = 1.f / (d2 + 1e-16f);
    float ws = 1.f / (w0 + w1 + w2);

    const int base = (b * N1 + n) * 3;
    g_w[base + 0] = w0 * ws;
    g_w[base + 1] = w1 * ws;
    g_w[base + 2] = w2 * ws;
    g_idx[base + 0] = i0;
    g_idx[base + 1] = i1;
    g_idx[base + 2] = i2;
}

// =========================================================================
// 2) Transpose x2 (B, C2, N2) -> (B, N2, C2)
// =========================================================================
__global__ void transpose_x2_kernel(const float* __restrict__ x2)
{
    __shared__ float tile[32][33];
    const int b  = blockIdx.z;
    const int c0 = blockIdx.y * 32;
    const int n0 = blockIdx.x * 32;
    const int tx = threadIdx.x;
    const int ty = threadIdx.y;

    #pragma unroll
    for (int i = ty; i < 32; i += 8)
        tile[i][tx] = x2[((size_t)b * C2 + c0 + i) * N2 + n0 + tx];
    __syncthreads();
    #pragma unroll
    for (int i = ty; i < 32; i += 8)
        g_x2t[((size_t)b * N2 + n0 + i) * C2 + c0 + tx] = tile[tx][i];
}

// =========================================================================
// 3) Gather + interpolate -> bf16 hi/lo planes of GEMM1 B (k in [128,384))
//    float4 loads, uint2 stores
// =========================================================================
__global__ void __launch_bounds__(256) gather_xb1_kernel()
{
    const int q    = blockIdx.x * 8 + (threadIdx.x >> 5);
    const int lane = threadIdx.x & 31;
    const int b = q / N1;
    const int n = q % N1;

    const int base = q * 3;
    const float w0 = g_w[base + 0];
    const float w1 = g_w[base + 1];
    const float w2 = g_w[base + 2];
    const float* f0 = g_x2t + ((size_t)b * N2 + g_idx[base + 0]) * C2;
    const float* f1 = g_x2t + ((size_t)b * N2 + g_idx[base + 1]) * C2;
    const float* f2 = g_x2t + ((size_t)b * N2 + g_idx[base + 2]) * C2;
    const size_t obase = ((size_t)b * N1 + n) * K1 + C1;

    #pragma unroll
    for (int it = 0; it < 2; ++it) {
        const int c = it * 128 + lane * 4;
        float4 a0 = *(const float4*)&f0[c];
        float4 a1 = *(const float4*)&f1[c];
        float4 a2 = *(const float4*)&f2[c];
        float v0 = fmaf(w0, a0.x, fmaf(w1, a1.x, w2 * a2.x));
        float v1 = fmaf(w0, a0.y, fmaf(w1, a1.y, w2 * a2.y));
        float v2 = fmaf(w0, a0.z, fmaf(w1, a1.z, w2 * a2.z));
        float v3 = fmaf(w0, a0.w, fmaf(w1, a1.w, w2 * a2.w));
        uint32_t h0, l0, h1, l1;
        split2(v0, v1, h0, l0);
        split2(v2, v3, h1, l1);
        *(uint2*)&g_xb1_hi[obase + c] = make_uint2(h0, h1);
        *(uint2*)&g_xb1_lo[obase + c] = make_uint2(l0, l1);
    }
}

// =========================================================================
// 4) Transpose-convert n-major fp32 -> k-contig bf16 hi/lo planes
//    phase 2 uses all 256 threads (4 k-values each, uint2 stores)
// =========================================================================
template<bool BN>
__global__ void convert_nmajor_kernel(const float* __restrict__ src,
                                      __nv_bfloat16* __restrict__ dhi,
                                      __nv_bfloat16* __restrict__ dlo,
                                      int C, int Kdst)
{
    __shared__ float tile[32][33];
    const int b  = blockIdx.z;
    const int c0 = blockIdx.y * 32;
    const int n0 = blockIdx.x * 32;
    const int tx = threadIdx.x;   // 32
    const int ty = threadIdx.y;   // 8

    #pragma unroll
    for (int i = ty; i < 32; i += 8) {
        float v = src[((size_t)b * C + c0 + i) * N1 + n0 + tx];
        if (BN) v = fmaxf(fmaf(v, g_scale[c0 + i], g_shift[c0 + i]), 0.f);
        tile[i][tx] = v;
    }
    __syncthreads();

    const int tid = ty * 32 + tx;
    const int r = tid >> 3;   // n row 0..31
    const int q = tid & 7;    // 4-k chunk 0..7
    uint32_t h0, l0, h1, l1;
    split2(tile[q * 4 + 0][r], tile[q * 4 + 1][r], h0, l0);
    split2(tile[q * 4 + 2][r], tile[q * 4 + 3][r], h1, l1);
    const size_t o = ((size_t)b * N1 + n0 + r) * Kdst + c0 + q * 4;
    *(uint2*)&dhi[o] = make_uint2(h0, h1);
    *(uint2*)&dlo[o] = make_uint2(l0, l1);
}

// =========================================================================
// 5) Convert BOTH weight tensors fp32 -> bf16 hi/lo in one launch
// =========================================================================
#define W1_TOT4 (M_OUT * K1 / 4)   // 24576
#define W2_TOT4 (M_OUT * K2 / 4)   // 16384

__global__ void convert_w_both_kernel(const float* __restrict__ W1s,
                                      const float* __restrict__ W2s,
                                      __nv_bfloat16* __restrict__ w1h,
                                      __nv_bfloat16* __restrict__ w1l,
                                      __nv_bfloat16* __restrict__ w2h,
                                      __nv_bfloat16* __restrict__ w2l)
{
    const int e = blockIdx.x * 256 + threadIdx.x;
    if (e >= W1_TOT4 + W2_TOT4) return;
    const bool first = (e < W1_TOT4);
    const int  idx   = first ? e : (e - W1_TOT4);
    float4 v = first ? ((const float4*)W1s)[idx] : ((const float4*)W2s)[idx];
    uint32_t h0, l0, h1, l1;
    split2(v.x, v.y, h0, l0);
    split2(v.z, v.w, h1, l1);
    if (first) {
        ((uint2*)w1h)[idx] = make_uint2(h0, h1);
        ((uint2*)w1l)[idx] = make_uint2(l0, l1);
    } else {
        ((uint2*)w2h)[idx] = make_uint2(h0, h1);
        ((uint2*)w2l)[idx] = make_uint2(l0, l1);
    }
}

// =========================================================================
// 6) bf16x3 GEMM: mma.sync + ldmatrix, cp.async 3-stage pipeline.
//    Block 128m x 64n, BK=32, 8 warps (4m x 2n), warp 32x32.
//    Epilogue accumulates per-channel BN stats via shfl + atomicAdd.
// =========================================================================
template<int K>
__global__ void __launch_bounds__(256) gemm_cp_kernel(
    const __nv_bfloat16* __restrict__ Ahi, const __nv_bfloat16* __restrict__ Alo,
    const float* __restrict__ bias,
    const __nv_bfloat16* __restrict__ Bhi, const __nv_bfloat16* __restrict__ Blo,
    float* __restrict__ Y, float* __restrict__ redS, float* __restrict__ redSS)
{
    constexpr int NT  = K / 32;
    constexpr int ASZ = 128 * 128;
    constexpr int BSZ = 64 * 128;
    constexpr int STG = ASZ + BSZ;   // 24576 per stage

    extern __shared__ __align__(16) unsigned char smem[];
    const uint32_t sb = smem_u32(smem);

    const int tid  = threadIdx.x;
    const int wid  = tid >> 5;
    const int lane = tid & 31;
    const int wm   = wid >> 1;
    const int wn   = wid & 1;

    const int b  = blockIdx.z;
    const int n0 = blockIdx.x * 64;
    const int m0 = blockIdx.y * 128;

    const size_t aoff = (size_t)m0 * K;
    const size_t boff = ((size_t)b * N1 + n0) * K;

    float acc[2][4][4];
    #pragma unroll
    for (int mt = 0; mt < 2; ++mt)
        #pragma unroll
        for (int nt = 0; nt < 4; ++nt)
            #pragma unroll
            for (int e = 0; e < 4; ++e) acc[mt][nt][e] = 0.f;

    auto load_tile = [&](int kt, int s) {
        const int k0 = kt * 32;
        const uint32_t As = sb + s * STG;
        const uint32_t Bs = As + ASZ;
        #pragma unroll
        for (int it = 0; it < 4; ++it) {
            const int idx = tid + it * 256;     // 0..1023
            const int r = idx >> 3, c = idx & 7;
            const __nv_bfloat16* src = (c < 4)
                ? Ahi + aoff + (size_t)r * K + k0 + c * 8
                : Alo + aoff + (size_t)r * K + k0 + (c - 4) * 8;
            CP16(As + swz(r, c), src);
        }
        #pragma unroll
        for (int it = 0; it < 2; ++it) {
            const int idx = tid + it * 256;     // 0..511
            const int r = idx >> 3, c = idx & 7;
            const __nv_bfloat16* src = (c < 4)
                ? Bhi + boff + (size_t)r * K + k0 + c * 8
                : Blo + boff + (size_t)r * K + k0 + (c - 4) * 8;
            CP16(Bs + swz(r, c), src);
        }
    };

    // ldmatrix lane addressing
    const int a_row  = (lane & 7) + ((lane >> 3) & 1) * 8;
    const int a_csel = lane >> 4;
    const int b_row  = lane & 7;
    const int b_sel  = lane >> 3;
    const int b_noff = (b_sel >> 1) * 8;
    const int b_csel = b_sel & 1;

    auto compute = [&](int s) {
        const uint32_t Asb = sb + s * STG;
        const uint32_t Bsb = Asb + ASZ;
        #pragma unroll
        for (int kk = 0; kk < 2; ++kk) {
            uint32_t a_hi[2][4], a_lo[2][4];
            uint32_t b_hi[4][2], b_lo[4][2];
            #pragma unroll
            for (int mt = 0; mt < 2; ++mt) {
                const int row = wm * 32 + mt * 16 + a_row;
                LDSM_X4(a_hi[mt], Asb + swz(row, kk * 2 + a_csel));
                LDSM_X4(a_lo[mt], Asb + swz(row, 4 + kk * 2 + a_csel));
            }
            #pragma unroll
            for (int g = 0; g < 2; ++g) {
                const int row = wn * 32 + g * 16 + b_noff + b_row;
                uint32_t t[4];
                LDSM_X4(t, Bsb + swz(row, kk * 2 + b_csel));
                b_hi[2 * g][0] = t[0]; b_hi[2 * g][1] = t[1];
                b_hi[2 * g + 1][0] = t[2]; b_hi[2 * g + 1][1] = t[3];
                LDSM_X4(t, Bsb + swz(row, 4 + kk * 2 + b_csel));
                b_lo[2 * g][0] = t[0]; b_lo[2 * g][1] = t[1];
                b_lo[2 * g + 1][0] = t[2]; b_lo[2 * g + 1][1] = t[3];
            }
            #pragma unroll
            for (int mt = 0; mt < 2; ++mt)
                #pragma unroll
                for (int nt = 0; nt < 4; ++nt) {
                    MMA16816(acc[mt][nt], a_hi[mt], b_hi[nt][0], b_hi[nt][1]);
                    MMA16816(acc[mt][nt], a_hi[mt], b_lo[nt][0], b_lo[nt][1]);
                    MMA16816(acc[mt][nt], a_lo[mt], b_hi[nt][0], b_hi[nt][1]);
                }
        }
    };

    load_tile(0, 0); CPCOMMIT();
    load_tile(1, 1); CPCOMMIT();

    for (int t = 0; t < NT; ++t) {
        CPWAIT1();
        __syncthreads();
        if (t + 2 < NT) load_tile(t + 2, (t + 2) % 3);
        CPCOMMIT();
        compute(t % 3);
    }

    // ---- epilogue: + bias, store, and accumulate BN stats ----
    const int lw = lane >> 2;
    const int ln = (lane & 3) * 2;
    #pragma unroll
    for (int mt = 0; mt < 2; ++mt) {
        #pragma unroll
        for (int h = 0; h < 2; ++h) {
            const int m = m0 + wm * 32 + mt * 16 + lw + h * 8;
            const float bi = bias[m];
            float* yrow = Y + ((size_t)b * M_OUT + m) * N1 + n0 + wn * 32;
            float s = 0.f, ss = 0.f;
            #pragma unroll
            for (int nt = 0; nt < 4; ++nt) {
                float v0 = acc[mt][nt][h * 2 + 0] + bi;
                float v1 = acc[mt][nt][h * 2 + 1] + bi;
                *(float2*)&yrow[nt * 8 + ln] = make_float2(v0, v1);
                s += v0 + v1;
                ss = fmaf(v0, v0, ss);
                ss = fmaf(v1, v1, ss);
            }
            s  += __shfl_xor_sync(0xffffffff, s, 1);
            ss += __shfl_xor_sync(0xffffffff, ss, 1);
            s  += __shfl_xor_sync(0xffffffff, s, 2);
            ss += __shfl_xor_sync(0xffffffff, ss, 2);
            if ((lane & 3) == 0) {
                atomicAdd(&redS[m], s);
                atomicAdd(&redSS[m], ss);
            }
        }
    }
}

// =========================================================================
// 7) BN finalize: (sum, sumsq) -> scale/shift
// =========================================================================
__global__ void bn_finalize_kernel(const float* __restrict__ gamma,
                                   const float* __restrict__ beta,
                                   const float* __restrict__ S,
                                   const float* __restrict__ SS)
{
    const int o = threadIdx.x;
    const float inv = 1.f / (float)(BB * N1);
    float mu  = S[o] * inv;
    float var = SS[o] * inv - mu * mu;
    float sc  = gamma[o] * rsqrtf(var + 1e-5f);
    g_scale[o] = sc;
    g_shift[o] = fmaf(-mu, sc, beta[o]);
}

// =========================================================================
// 8) BN apply + ReLU (final output only)
// =========================================================================
__global__ void __launch_bounds__(256) bn_apply_kernel(float* __restrict__ Y)
{
    const size_t base = ((size_t)blockIdx.x * 256 + threadIdx.x) * 4;
    if (base >= (size_t)TOT) return;
    const int o = (int)((base / N1) % M_OUT);
    const float sc = g_scale[o];
    const float sf = g_shift[o];
    float4 v = *(float4*)&Y[base];
    v.x = fmaxf(fmaf(v.x, sc, sf), 0.f);
    v.y = fmaxf(fmaf(v.y, sc, sf), 0.f);
    v.z = fmaxf(fmaf(v.z, sc, sf), 0.f);
    v.w = fmaxf(fmaf(v.w, sc, sf), 0.f);
    *(float4*)&Y[base] = v;
}

// =========================================================================
// launcher
// =========================================================================
extern "C" void kernel_launch(void* const* d_in, const int* in_sizes, int n_in,
                              void* d_out, int out_size)
{
    const float* p1  = (const float*)d_in[0];
    const float* x1  = (const float*)d_in[1];
    const float* p2  = (const float*)d_in[2];
    const float* x2  = (const float*)d_in[3];
    const float* W1  = (const float*)d_in[4];
    const float* b1  = (const float*)d_in[5];
    const float* g1  = (const float*)d_in[6];
    const float* be1 = (const float*)d_in[7];
    const float* W2  = (const float*)d_in[8];
    const float* b2  = (const float*)d_in[9];
    const float* g2  = (const float*)d_in[10];
    const float* be2 = (const float*)d_in[11];
    float* out = (float*)d_out;

    float* y1;  cudaGetSymbolAddress((void**)&y1, g_y1);
    float *s1, *ss1, *s2, *ss2;
    cudaGetSymbolAddress((void**)&s1,  g_s1);
    cudaGetSymbolAddress((void**)&ss1, g_ss1);
    cudaGetSymbolAddress((void**)&s2,  g_s2);
    cudaGetSymbolAddress((void**)&ss2, g_ss2);
    __nv_bfloat16 *xb1h, *xb1l, *xb2h, *xb2l, *w1h, *w1l, *w2h, *w2l;
    cudaGetSymbolAddress((void**)&xb1h, g_xb1_hi);
    cudaGetSymbolAddress((void**)&xb1l, g_xb1_lo);
    cudaGetSymbolAddress((void**)&xb2h, g_xb2_hi);
    cudaGetSymbolAddress((void**)&xb2l, g_xb2_lo);
    cudaGetSymbolAddress((void**)&w1h, g_w1_hi);
    cudaGetSymbolAddress((void**)&w1l, g_w1_lo);
    cudaGetSymbolAddress((void**)&w2h, g_w2_hi);
    cudaGetSymbolAddress((void**)&w2l, g_w2_lo);

    const int smem_bytes = 3 * (128 * 128 + 64 * 128);  // 73728
    cudaFuncSetAttribute(gemm_cp_kernel<K1>,
                         cudaFuncAttributeMaxDynamicSharedMemorySize, smem_bytes);
    cudaFuncSetAttribute(gemm_cp_kernel<K2>,
                         cudaFuncAttributeMaxDynamicSharedMemorySize, smem_bytes);

    // 1) KNN (also zeros BN accumulators in block (0,0))
    knn_kernel<<<dim3(N1 / 128, BB), 128>>>(p1, p2);
    // 2) transpose x2
    transpose_x2_kernel<<<dim3(N2 / 32, C2 / 32, BB), dim3(32, 8)>>>(x2);
    // 3) both weight conversions, one launch
    convert_w_both_kernel<<<(W1_TOT4 + W2_TOT4 + 255) / 256, 256>>>(
        W1, W2, w1h, w1l, w2h, w2l);
    // 4) B1 planes: x1 part (k<128) + gathered interp part (k in [128,384))
    convert_nmajor_kernel<false><<<dim3(N1 / 32, C1 / 32, BB), dim3(32, 8)>>>(x1, xb1h, xb1l, C1, K1);
    gather_xb1_kernel<<<(BB * N1) / 8, 256>>>();
    // 5) GEMM1 -> y1 fp32 (raw + bias) + BN1 stats
    gemm_cp_kernel<K1><<<dim3(N1 / 64, 2, BB), 256, smem_bytes>>>(w1h, w1l, b1, xb1h, xb1l, y1, s1, ss1);
    // 6) BN1 finalize
    bn_finalize_kernel<<<1, M_OUT>>>(g1, be1, s1, ss1);
    // 7) B2 planes: BN1(y1)+ReLU, transpose-converted
    convert_nmajor_kernel<true><<<dim3(N1 / 32, M_OUT / 32, BB), dim3(32, 8)>>>(y1, xb2h, xb2l, M_OUT, K2);
    // 8) GEMM2 -> out (raw + bias) + BN2 stats
    gemm_cp_kernel<K2><<<dim3(N1 / 64, 2, BB), 256, smem_bytes>>>(w2h, w2l, b2, xb2h, xb2l, out, s2, ss2);
    // 9) BN2 finalize + apply
    bn_finalize_kernel<<<1, M_OUT>>>(g2, be2, s2, ss2);
    bn_apply_kernel<<<TOT / 1024, 256>>>(out);
}